// round 1
// baseline (speedup 1.0000x reference)
#include <cuda_runtime.h>
#include <cstddef>

// Problem dims (fixed)
#define T_DIM 512
#define B_DIM 32
#define I_DIM 512
#define H_DIM 512
#define M_DIM (T_DIM * B_DIM)   // 16384 rows of gx
#define N_DIM (3 * H_DIM)       // 1536 cols of gx
#define K_DIM I_DIM             // 512 reduction

// Scratch for gx = x @ W_ih^T, (M, N) row-major. 100.7 MB static device array
// (allocation-free per harness rules).
__device__ float g_gx[(size_t)M_DIM * N_DIM];

// ---------------------------------------------------------------------------
// GEMM: C[m][n] = sum_k A[m][k] * W[n][k]
// A = x flattened (M, K) row-major; W = W_ih (N, K) row-major. Both K-major (NT gemm).
// 128x128 block tile, BK=16, 256 threads, 8x8 per-thread microtile, 2 CTAs/SM.
// ---------------------------------------------------------------------------
__global__ __launch_bounds__(256, 2)
void indgru_gemm_kernel(const float* __restrict__ A, const float* __restrict__ W)
{
    __shared__ float As[16][128];
    __shared__ float Ws[16][128];

    const int tid = threadIdx.x;
    const int bx  = blockIdx.x;   // n-tile: 0..11
    const int by  = blockIdx.y;   // m-tile: 0..127

    // Global-load assignment: each thread loads 2 float4 from A and 2 from W per tile.
    const int lrow = tid >> 2;          // 0..63
    const int lc4  = (tid & 3) * 4;     // 0,4,8,12 (k offset within tile)

    const float* Aptr = A + (size_t)(by * 128 + lrow) * K_DIM + lc4;
    const float* Wptr = W + (size_t)(bx * 128 + lrow) * K_DIM + lc4;

    const int tx8 = (tid & 15) * 8;     // n within tile
    const int ty8 = (tid >> 4) * 8;     // m within tile

    float acc[8][8];
#pragma unroll
    for (int i = 0; i < 8; i++)
#pragma unroll
        for (int j = 0; j < 8; j++) acc[i][j] = 0.0f;

    for (int k0 = 0; k0 < K_DIM; k0 += 16) {
        // Issue global loads for this tile
        const float4 a0 = *(const float4*)(Aptr + k0);
        const float4 a1 = *(const float4*)(Aptr + (size_t)64 * K_DIM + k0);
        const float4 w0 = *(const float4*)(Wptr + k0);
        const float4 w1 = *(const float4*)(Wptr + (size_t)64 * K_DIM + k0);

        __syncthreads();   // previous tile's compute done before overwrite

        // Transposed store into SMEM: As[k][m], Ws[k][n]
        As[lc4 + 0][lrow] = a0.x;  As[lc4 + 1][lrow] = a0.y;
        As[lc4 + 2][lrow] = a0.z;  As[lc4 + 3][lrow] = a0.w;
        As[lc4 + 0][lrow + 64] = a1.x;  As[lc4 + 1][lrow + 64] = a1.y;
        As[lc4 + 2][lrow + 64] = a1.z;  As[lc4 + 3][lrow + 64] = a1.w;

        Ws[lc4 + 0][lrow] = w0.x;  Ws[lc4 + 1][lrow] = w0.y;
        Ws[lc4 + 2][lrow] = w0.z;  Ws[lc4 + 3][lrow] = w0.w;
        Ws[lc4 + 0][lrow + 64] = w1.x;  Ws[lc4 + 1][lrow + 64] = w1.y;
        Ws[lc4 + 2][lrow + 64] = w1.z;  Ws[lc4 + 3][lrow + 64] = w1.w;

        __syncthreads();

#pragma unroll
        for (int k = 0; k < 16; k++) {
            float a[8], w[8];
            *(float4*)(a + 0) = *(const float4*)&As[k][ty8];
            *(float4*)(a + 4) = *(const float4*)&As[k][ty8 + 4];
            *(float4*)(w + 0) = *(const float4*)&Ws[k][tx8];
            *(float4*)(w + 4) = *(const float4*)&Ws[k][tx8 + 4];
#pragma unroll
            for (int i = 0; i < 8; i++)
#pragma unroll
                for (int j = 0; j < 8; j++)
                    acc[i][j] = fmaf(a[i], w[j], acc[i][j]);
        }
    }

    // Store to gx scratch
    float* Cb = g_gx + (size_t)(by * 128 + ty8) * N_DIM + bx * 128 + tx8;
#pragma unroll
    for (int i = 0; i < 8; i++) {
        float4 v0 = make_float4(acc[i][0], acc[i][1], acc[i][2], acc[i][3]);
        float4 v1 = make_float4(acc[i][4], acc[i][5], acc[i][6], acc[i][7]);
        *(float4*)(Cb + (size_t)i * N_DIM)     = v0;
        *(float4*)(Cb + (size_t)i * N_DIM + 4) = v1;
    }
}

// ---------------------------------------------------------------------------
// Scan: one thread per (b, h) element; 512 sequential GRU steps each.
// gx layout: (T, B, 3H) row-major, split as [r | z | n] along last dim.
// out layout: first T*B*H = all hidden states; then B*H = final state.
// ---------------------------------------------------------------------------
__global__ __launch_bounds__(128)
void indgru_scan_kernel(const float* __restrict__ h0,
                        const float* __restrict__ w_hh,
                        float* __restrict__ out)
{
    const int idx = blockIdx.x * blockDim.x + threadIdx.x;  // 0..16383
    const int b  = idx >> 9;        // / H_DIM
    const int hh = idx & (H_DIM - 1);

    float h = h0[idx];
    const float wr = w_hh[hh];
    const float wz = w_hh[H_DIM + hh];
    const float wn = w_hh[2 * H_DIM + hh];

    const float* g = g_gx + (size_t)b * N_DIM + hh;

#pragma unroll 4
    for (int t = 0; t < T_DIM; t++) {
        const float* gt = g + (size_t)t * B_DIM * N_DIM;
        const float gr = gt[0];
        const float gz = gt[H_DIM];
        const float gn = gt[2 * H_DIM];

        const float r = 1.0f / (1.0f + __expf(-(gr + wr * h)));
        const float z = 1.0f / (1.0f + __expf(-(gz + wz * h)));
        const float n = tanhf(gn + r * (wn * h));
        h = (1.0f - z) * n + z * h;

        out[(size_t)(t * B_DIM + b) * H_DIM + hh] = h;
    }
    // h_last tail
    out[(size_t)T_DIM * B_DIM * H_DIM + idx] = h;
}

// ---------------------------------------------------------------------------
// Launch
// ---------------------------------------------------------------------------
extern "C" void kernel_launch(void* const* d_in, const int* in_sizes, int n_in,
                              void* d_out, int out_size)
{
    const float* x    = (const float*)d_in[0];   // (T, B, I)
    const float* h0   = (const float*)d_in[1];   // (B, H)
    const float* W_ih = (const float*)d_in[2];   // (3H, I)
    const float* w_hh = (const float*)d_in[3];   // (3, H)
    float* out = (float*)d_out;

    dim3 ggrid(N_DIM / 128, M_DIM / 128);        // (12, 128)
    indgru_gemm_kernel<<<ggrid, 256>>>(x, W_ih);

    indgru_scan_kernel<<<128, 128>>>(h0, w_hh, out);
}

// round 8
// speedup vs baseline: 4.1563x; 4.1563x over previous
#include <cuda_runtime.h>
#include <cuda_bf16.h>
#include <cstdint>
#include <cstddef>

// Problem dims (fixed)
#define T_DIM 512
#define B_DIM 32
#define I_DIM 512
#define H_DIM 512
#define M_DIM (T_DIM * B_DIM)   // 16384
#define N_DIM (3 * H_DIM)       // 1536
#define K_DIM I_DIM             // 512

// ---------------------------------------------------------------------------
// Device scratch (allocation-free per harness rules)
// ---------------------------------------------------------------------------
__device__ float         g_gx[(size_t)M_DIM * N_DIM];   // 100.7 MB
__device__ __nv_bfloat16 g_Ah[(size_t)M_DIM * K_DIM];   // 16 MB
__device__ __nv_bfloat16 g_Al[(size_t)M_DIM * K_DIM];   // 16 MB
__device__ __nv_bfloat16 g_Wh[(size_t)N_DIM * K_DIM];   // 1.5 MB
__device__ __nv_bfloat16 g_Wl[(size_t)N_DIM * K_DIM];   // 1.5 MB

// ---------------------------------------------------------------------------
// PTX wrappers: mma.sync (HMMA, sm_80+ -> valid on plain sm_103 target),
// cp.async (LDGSTS). NO tcgen05 — ptxas rejects it on the non-'a' target.
// ---------------------------------------------------------------------------
__device__ __forceinline__ uint32_t smem_u32(const void* p) {
    uint32_t a;
    asm("{ .reg .u64 t; cvta.to.shared.u64 t, %1; cvt.u32.u64 %0, t; }"
        : "=r"(a) : "l"(p));
    return a;
}

__device__ __forceinline__ void cp16(uint32_t dst, const void* src) {
    asm volatile("cp.async.cg.shared.global [%0], [%1], 16;"
                 :: "r"(dst), "l"(src));
}
#define CP_COMMIT() asm volatile("cp.async.commit_group;" ::: "memory")
#define CP_WAIT_1() asm volatile("cp.async.wait_group 1;" ::: "memory")
#define CP_WAIT_0() asm volatile("cp.async.wait_group 0;" ::: "memory")

__device__ __forceinline__ void mma16816(float* d, const uint32_t* a,
                                         const uint32_t* b, const float* c) {
    asm volatile(
        "mma.sync.aligned.m16n8k16.row.col.f32.bf16.bf16.f32 "
        "{%0,%1,%2,%3}, {%4,%5,%6,%7}, {%8,%9}, {%10,%11,%12,%13};"
        : "=f"(d[0]), "=f"(d[1]), "=f"(d[2]), "=f"(d[3])
        : "r"(a[0]), "r"(a[1]), "r"(a[2]), "r"(a[3]),
          "r"(b[0]), "r"(b[1]),
          "f"(c[0]), "f"(c[1]), "f"(c[2]), "f"(c[3]));
}

// ---------------------------------------------------------------------------
// fp32 -> bf16 hi/lo split
// ---------------------------------------------------------------------------
__global__ __launch_bounds__(256)
void split_bf16_kernel(const float* __restrict__ src,
                       __nv_bfloat16* __restrict__ hi,
                       __nv_bfloat16* __restrict__ lo, int n4)
{
    int i = blockIdx.x * blockDim.x + threadIdx.x;
    if (i >= n4) return;
    float4 v = ((const float4*)src)[i];
    float vv[4] = {v.x, v.y, v.z, v.w};
    __nv_bfloat16 h[4], l[4];
#pragma unroll
    for (int j = 0; j < 4; j++) {
        h[j] = __float2bfloat16(vv[j]);
        l[j] = __float2bfloat16(vv[j] - __bfloat162float(h[j]));
    }
    ((uint2*)hi)[i] = *(uint2*)h;
    ((uint2*)lo)[i] = *(uint2*)l;
}

// ---------------------------------------------------------------------------
// HMMA bf16 split GEMM: gx = A @ W^T, effective K = 3*512
// CTA tile 128(M) x 128(N), BK = 64, 256 threads (8 warps, 2x4 warp grid),
// warp tile 64x32, double-buffered SMEM via cp.async.
// SMEM rows padded to 72 bf16 (144 B) -> bank-conflict-free fragment loads.
// ---------------------------------------------------------------------------
#define BK 64
#define TILE_M 128
#define TILE_N 128
#define NSTEP 24                 // 3 passes * (512 / 64)
#define ROW_ELEMS 72             // 64 + 8 pad
#define ROW_BYTES (ROW_ELEMS * 2)        // 144
#define TILE_BYTES (128 * ROW_BYTES)     // 18432 per matrix per buffer
#define SM_TOTAL (4 * TILE_BYTES)        // 73728: A0,B0,A1,B1

__global__ __launch_bounds__(256, 2)
void indgru_gemm_hmma()
{
    extern __shared__ char smem[];
    const uint32_t sb = smem_u32(smem);
    const int tid  = threadIdx.x;
    const int lane = tid & 31;
    const int wid  = tid >> 5;
    const int bx = blockIdx.x;   // n-tile 0..11
    const int by = blockIdx.y;   // m-tile 0..127

    const int wm = (wid & 1) * 64;   // warp m-offset in CTA tile
    const int wn = (wid >> 1) * 32;  // warp n-offset

    // Per-thread cp.async assignments: 4 A-chunks + 4 B-chunks of 16B per step
    // chunk ch = tid + i*256 : m = ch>>3, kq = ch&7  (kq = 8-elem group)
    const int r_frag = lane >> 2;          // 0..7
    const int c_frag = (lane & 3) * 2;     // 0,2,4,6

    float acc[4][4][4];
#pragma unroll
    for (int mt = 0; mt < 4; mt++)
#pragma unroll
        for (int nt = 0; nt < 4; nt++)
#pragma unroll
            for (int j = 0; j < 4; j++) acc[mt][nt][j] = 0.0f;

    // ---- tile loader (cp.async into buffer s&1) ----
    auto load_tile = [&](int s) {
        const int p  = s >> 3;                 // pass 0,1,2
        const int k0 = (s & 7) * BK;
        const __nv_bfloat16* Asrc = (p < 2) ? g_Ah : g_Al;
        const __nv_bfloat16* Wsrc = (p == 1) ? g_Wl : g_Wh;
        const uint32_t aB = sb + (s & 1) * (2 * TILE_BYTES);
        const uint32_t bB = aB + TILE_BYTES;
#pragma unroll
        for (int i = 0; i < 4; i++) {
            const int ch = tid + i * 256;
            const int m  = ch >> 3;
            const int kq = ch & 7;
            const uint32_t doff = (uint32_t)(m * ROW_BYTES + kq * 16);
            cp16(aB + doff, Asrc + (size_t)(by * TILE_M + m) * K_DIM + k0 + kq * 8);
            cp16(bB + doff, Wsrc + (size_t)(bx * TILE_N + m) * K_DIM + k0 + kq * 8);
        }
        CP_COMMIT();
    };

    load_tile(0);

    for (int s = 0; s < NSTEP; s++) {
        if (s + 1 < NSTEP) {
            load_tile(s + 1);
            CP_WAIT_1();
        } else {
            CP_WAIT_0();
        }
        __syncthreads();

        const __nv_bfloat16* As =
            (const __nv_bfloat16*)(smem + (s & 1) * (2 * TILE_BYTES));
        const __nv_bfloat16* Bs =
            (const __nv_bfloat16*)(smem + (s & 1) * (2 * TILE_BYTES) + TILE_BYTES);

#pragma unroll
        for (int kk = 0; kk < 4; kk++) {
            const int c = kk * 16 + c_frag;
            uint32_t afr[4][4];
#pragma unroll
            for (int mt = 0; mt < 4; mt++) {
                const int r = wm + mt * 16 + r_frag;
                afr[mt][0] = *(const uint32_t*)&As[r * ROW_ELEMS + c];
                afr[mt][1] = *(const uint32_t*)&As[(r + 8) * ROW_ELEMS + c];
                afr[mt][2] = *(const uint32_t*)&As[r * ROW_ELEMS + c + 8];
                afr[mt][3] = *(const uint32_t*)&As[(r + 8) * ROW_ELEMS + c + 8];
            }
            uint32_t bfr[4][2];
#pragma unroll
            for (int nt = 0; nt < 4; nt++) {
                const int n = wn + nt * 8 + r_frag;
                bfr[nt][0] = *(const uint32_t*)&Bs[n * ROW_ELEMS + c];
                bfr[nt][1] = *(const uint32_t*)&Bs[n * ROW_ELEMS + c + 8];
            }
#pragma unroll
            for (int mt = 0; mt < 4; mt++)
#pragma unroll
                for (int nt = 0; nt < 4; nt++)
                    mma16816(acc[mt][nt], afr[mt], bfr[nt], acc[mt][nt]);
        }
        __syncthreads();
    }

    // ---- epilogue: acc -> g_gx ----
#pragma unroll
    for (int mt = 0; mt < 4; mt++) {
        const int r0 = by * TILE_M + wm + mt * 16 + r_frag;
#pragma unroll
        for (int nt = 0; nt < 4; nt++) {
            const int c0 = bx * TILE_N + wn + nt * 8 + c_frag;
            float2 v0 = make_float2(acc[mt][nt][0], acc[mt][nt][1]);
            float2 v1 = make_float2(acc[mt][nt][2], acc[mt][nt][3]);
            *(float2*)(g_gx + (size_t)r0 * N_DIM + c0)       = v0;
            *(float2*)(g_gx + (size_t)(r0 + 8) * N_DIM + c0) = v1;
        }
    }
}

// ---------------------------------------------------------------------------
// Scan: one thread per (b,h); MUFU.TANH nonlinearities + depth-8 prefetch
// ---------------------------------------------------------------------------
__device__ __forceinline__ float tanh_ap(float x) {
    float y;
    asm("tanh.approx.f32 %0, %1;" : "=f"(y) : "f"(x));
    return y;
}

__global__ __launch_bounds__(128)
void indgru_scan_kernel(const float* __restrict__ h0,
                        const float* __restrict__ w_hh,
                        float* __restrict__ out)
{
    const int idx = blockIdx.x * 128 + threadIdx.x;  // 0..16383
    const int b  = idx >> 9;
    const int hh = idx & (H_DIM - 1);

    float h = h0[idx];
    const float wr = w_hh[hh];
    const float wz = w_hh[H_DIM + hh];
    const float wn = w_hh[2 * H_DIM + hh];

    const float* g = g_gx + (size_t)b * N_DIM + hh;
    const size_t gstride = (size_t)B_DIM * N_DIM;   // per-t stride in gx
    float* op = out + (size_t)b * H_DIM + hh;       // per-t stride B*H

    float pr[8], pz[8], pn[8];
#pragma unroll
    for (int d = 0; d < 8; d++) {
        const float* gt = g + (size_t)d * gstride;
        pr[d] = __ldg(gt);
        pz[d] = __ldg(gt + H_DIM);
        pn[d] = __ldg(gt + 2 * H_DIM);
    }

#pragma unroll 8
    for (int t = 0; t < T_DIM; t++) {
        const int sl = t & 7;
        const float gr = pr[sl], gz = pz[sl], gn = pn[sl];
        if (t + 8 < T_DIM) {
            const float* gt = g + (size_t)(t + 8) * gstride;
            pr[sl] = __ldg(gt);
            pz[sl] = __ldg(gt + H_DIM);
            pn[sl] = __ldg(gt + 2 * H_DIM);
        }
        // sigmoid(x) = 0.5*tanh(0.5x) + 0.5  (one MUFU each)
        const float r = fmaf(0.5f, tanh_ap(0.5f * fmaf(wr, h, gr)), 0.5f);
        const float z = fmaf(0.5f, tanh_ap(0.5f * fmaf(wz, h, gz)), 0.5f);
        const float n = tanh_ap(fmaf(r, wn * h, gn));
        h = fmaf(z, h - n, n);   // (1-z)*n + z*h
        op[(size_t)t * (B_DIM * H_DIM)] = h;
    }
    out[(size_t)T_DIM * B_DIM * H_DIM + idx] = h;   // h_last
}

// ---------------------------------------------------------------------------
// Launch
// ---------------------------------------------------------------------------
extern "C" void kernel_launch(void* const* d_in, const int* in_sizes, int n_in,
                              void* d_out, int out_size)
{
    const float* x    = (const float*)d_in[0];   // (T, B, I)
    const float* h0   = (const float*)d_in[1];   // (B, H)
    const float* W_ih = (const float*)d_in[2];   // (3H, I)
    const float* w_hh = (const float*)d_in[3];   // (3, H)
    float* out = (float*)d_out;

    __nv_bfloat16 *ah, *al, *wh, *wl;
    cudaGetSymbolAddress((void**)&ah, g_Ah);
    cudaGetSymbolAddress((void**)&al, g_Al);
    cudaGetSymbolAddress((void**)&wh, g_Wh);
    cudaGetSymbolAddress((void**)&wl, g_Wl);

    {
        int n4 = M_DIM * K_DIM / 4;   // 2097152
        split_bf16_kernel<<<n4 / 256, 256>>>(x, ah, al, n4);
    }
    {
        int n4 = N_DIM * K_DIM / 4;   // 196608
        split_bf16_kernel<<<n4 / 256, 256>>>(W_ih, wh, wl, n4);
    }

    cudaFuncSetAttribute(indgru_gemm_hmma,
                         cudaFuncAttributeMaxDynamicSharedMemorySize, SM_TOTAL);
    dim3 ggrid(N_DIM / TILE_N, M_DIM / TILE_M);   // (12, 128)
    indgru_gemm_hmma<<<ggrid, 256, SM_TOTAL>>>();

    indgru_scan_kernel<<<M_DIM / 128, 128>>>(h0, w_hh, out);
}